// round 12
// baseline (speedup 1.0000x reference)
#include <cuda_runtime.h>
#include <cuda_fp16.h>
#include <math.h>
#include <stdint.h>

// ---------------- problem constants ----------------
#define RR    32
#define LLEN  63
#define HH    256
#define MTOT  2048
#define NG    6
#define NTOT  1536
#define KW0   576            // layer0 K: 512 h + 64 x-pad (8 real)
#define KW1   1024           // layer1 K: 512 h + 512 x1
#define NC0   18             // k32 chunks
#define NC1   32
#define OFF1  66060288ull
#define OFF2  67108864ull
#define NCTA  256

// ---------------- device scratch ----------------
// z-state rows: 1024 fp16 = [hi 512 | lo 512]; hi = [h_row 256 | h_col 256]
__device__ __half g_zh[2][2][MTOT * 1024];                 // [layer][buf]
__device__ __half g_x1[(size_t)LLEN * MTOT * 512];         // layer1 x rows (hi only)
__device__ __half g_x0[LLEN * MTOT * 64];                  // layer0 x rows (hi only)
__device__ __half g_w0[NTOT * KW0];
__device__ __half g_w1[NTOT * KW1];
__device__ int g_bar_count = 0;
__device__ int g_bar_gen = 0;

// ---------------- helpers ----------------
__device__ __forceinline__ uint32_t smem_u32(const void* p) {
    uint32_t a;
    asm("{ .reg .u64 t; cvta.to.shared.u64 t, %1; cvt.u32.u64 %0, t; }" : "=r"(a) : "l"(p));
    return a;
}
__device__ __forceinline__ void cp16(uint32_t s, const void* g) {
    asm volatile("cp.async.cg.shared.global [%0], [%1], 16;" :: "r"(s), "l"(g));
}
#define CP_COMMIT() asm volatile("cp.async.commit_group;")
#define CP_WAIT2()  asm volatile("cp.async.wait_group 2;")
#define CP_WAIT0()  asm volatile("cp.async.wait_group 0;")

#define MMA(accp, a, b0, b1) \
    asm volatile("mma.sync.aligned.m16n8k16.row.col.f32.f16.f16.f32 " \
        "{%0,%1,%2,%3}, {%4,%5,%6,%7}, {%8,%9}, {%0,%1,%2,%3};" \
        : "+f"((accp)[0]), "+f"((accp)[1]), "+f"((accp)[2]), "+f"((accp)[3]) \
        : "r"((a)[0]), "r"((a)[1]), "r"((a)[2]), "r"((a)[3]), "r"(b0), "r"(b1))

#define LDSM4(r, addr) \
    asm volatile("ldmatrix.sync.aligned.m8n8.x4.shared.b16 {%0,%1,%2,%3}, [%4];" \
        : "=r"((r)[0]), "=r"((r)[1]), "=r"((r)[2]), "=r"((r)[3]) : "r"(addr))

__device__ __forceinline__ float sigmoidf_(float x) { return 1.0f / (1.0f + __expf(-x)); }
__device__ __forceinline__ uint32_t hpack(float x, float y) {
    __half2 p = __floats2half2_rn(x, y);
    return *reinterpret_cast<uint32_t*>(&p);
}
// L2-coherent load of a half2 (L1 not coherent across SMs inside one launch)
__device__ __forceinline__ float2 ldcg_h2(const __half* p) {
    uint32_t u;
    asm volatile("ld.global.cg.u32 %0, [%1];" : "=r"(u) : "l"(p));
    __half2 h = *reinterpret_cast<__half2*>(&u);
    return __half22float2(h);
}

// ---------------- smem layout (per stage): k32 chunks, rows padded to 80B ----------------
#define BM 128
#define BJ 16
#define S_A  0                 // A: 128 rows x 80B = 10240
#define S_B  10240             // B: 96 rows x 80B = 7680
#define STAGE 17920
#define NSTAGE 6
#define SMEMT (NSTAGE * STAGE) // 107520 -> 2 CTAs/SM (215KB of 228KB)

// ---------------- prep kernels ----------------
__global__ void prep_w(const float* __restrict__ Wf, const float* __restrict__ Wo) {
    const int N0 = NTOT * KW0, N1 = NTOT * KW1;
    for (int i = blockIdx.x * blockDim.x + threadIdx.x; i < N0 + N1; i += gridDim.x * blockDim.x) {
        if (i < N0) {
            int n = i / KW0, k = i % KW0;
            float v = (k < 520) ? Wf[(size_t)n * 520 + k] : 0.0f;
            g_w0[i] = __float2half_rn(v);
        } else {
            g_w1[i - N0] = __float2half_rn(Wo[i - N0]);
        }
    }
}

__global__ void prep_x0(const float* __restrict__ inp) {
    const int TOT = LLEN * MTOT * 64;
    for (int i = blockIdx.x * blockDim.x + threadIdx.x; i < TOT; i += gridDim.x * blockDim.x) {
        int k = i & 63;
        int M = (i >> 6) & (MTOT - 1);
        int t = i >> 17;
        int r = M >> 6, b = M & 63, c = t - r;
        float v = 0.0f;
        if (k < 8 && c >= 0 && c < 32)
            v = inp[(((size_t)b * RR + r) * 32 + c) * 8 + k];
        g_x0[i] = __float2half_rn(v);
    }
}

// zero BOTH z double-buffers; inactive rows rely on persistent zeros
__global__ void init_all() {
    int i = blockIdx.x * blockDim.x + threadIdx.x;
    __half z = __float2half_rn(0.0f);
    if (i < MTOT * 1024) {
        g_zh[0][0][i] = z; g_zh[0][1][i] = z;
        g_zh[1][0][i] = z; g_zh[1][1][i] = z;
    }
}
// t<r triangle of output_all is never written by active tiles -> zero it once
__global__ void zero_tri(float* __restrict__ dout) {
    const int M = blockIdx.x;
    const int r = M >> 6;
    float* base = dout + (size_t)M * LLEN * 512;
    const int n = r * 512;
    for (int i = threadIdx.x; i < n; i += blockDim.x) base[i] = 0.0f;
}

// ---------------- grid-wide barrier (all 256 CTAs resident by construction) ----------------
__device__ __forceinline__ void grid_barrier() {
    __threadfence();
    __syncthreads();
    if (threadIdx.x == 0) {
        int my = atomicAdd(&g_bar_gen, 0);
        int tk = atomicAdd(&g_bar_count, 1);
        if (tk == NCTA - 1) {
            atomicExch(&g_bar_count, 0);
            __threadfence();
            atomicAdd(&g_bar_gen, 1);
        } else {
            while (atomicAdd(&g_bar_gen, 0) == my) __nanosleep(64);
        }
        __threadfence();
    }
    __syncthreads();
}

// ---------------- one fused GEMM+pointwise tile ----------------
__device__ __forceinline__ void do_tile(
    int layer, int t, int m0, int jb, char* sm,
    const float* __restrict__ BiasAll, float* __restrict__ dout)
{
    const uint32_t sbase = smem_u32(sm);
    const int tid = threadIdx.x;
    const int lane = tid & 31, w = tid >> 5;
    const int par = t & 1;
    const int nc = layer ? NC1 : NC0;
    const int kw = layer ? KW1 : KW0;
    // upper 64 rows (r = m0/64 + 1) inactive when t == m0/64 -> warps 4-7 skip math
    const bool mywork = (w < 4) || (t > (m0 >> 6));

    float acc[NG][2][4];
#pragma unroll
    for (int g = 0; g < NG; ++g)
#pragma unroll
        for (int nt = 0; nt < 2; ++nt)
#pragma unroll
            for (int q = 0; q < 4; ++q) acc[g][nt][q] = 0.0f;

    {
        const __half* W = layer ? g_w1 : g_w0;

        // ---- cp.async coords ----
        const int lr = tid >> 2;        // 0..63
        const int lc = tid & 3;         // 16B piece of the 64B chunk-row
        const char* pZ = (const char*)g_zh[layer][par] + (size_t)(m0 + lr) * 2048 + lc * 16;
        const int xstride = layer ? 1024 : 128;
        const char* pX = (layer ? (const char*)g_x1 + ((size_t)t * MTOT) * 1024
                                : (const char*)g_x0 + ((size_t)t * MTOT) * 128)
                         + (size_t)(m0 + lr) * xstride + lc * 16;
        const uint32_t sAoff = S_A + lr * 80 + lc * 16;

        int wr0 = (lr >> 4) * 256 + jb + (lr & 15);
        int v1 = 64 + lr;
        int wr1 = (v1 >> 4) * 256 + jb + (v1 & 15);
        const char* gB0 = (const char*)(W + (size_t)wr0 * kw) + lc * 16;
        const char* gB1 = (const char*)(W + (size_t)wr1 * kw) + lc * 16;
        const uint32_t sB0 = S_B + lr * 80 + lc * 16;
        const uint32_t sB1 = S_B + v1 * 80 + lc * 16;
        const bool doB1 = (lr < 32);

        auto issue = [&](int c) {
            const uint32_t sb = sbase + (c % NSTAGE) * STAGE;
            const char* a = (c < 16) ? pZ + (size_t)c * 64
                                     : pX + (size_t)(c - 16) * 64;
            cp16(sb + sAoff, a);
            cp16(sb + sAoff + 64 * 80, a + ((c < 16) ? 64 * 2048 : 64 * xstride));
            const size_t go = (size_t)c * 64;
            cp16(sb + sB0, gB0 + go);
            if (doB1) cp16(sb + sB1, gB1 + go);
            CP_COMMIT();
        };

        // ---- ldmatrix lane coords (warp = m16 x n16) ----
        const int aRow = (lane & 7) + ((lane >> 3) & 1) * 8;
        const int aKoff = ((lane >> 4) & 1) * 16;
        const int bRow = (lane & 7) + (((lane >> 4) & 1) ? 8 : 0);
        const int bKoff = ((lane >> 3) & 1) * 16;
        const uint32_t aBase = (w * 16 + aRow) * 80 + aKoff;
        const uint32_t bBase = bRow * 80 + bKoff;

        auto compute = [&](int buf) {
            const uint32_t S = sbase + buf * STAGE;
#pragma unroll
            for (int h = 0; h < 2; ++h) {
                uint32_t a[4];
                LDSM4(a, S + S_A + aBase + h * 32);
#pragma unroll
                for (int g = 0; g < NG; ++g) {
                    uint32_t b[4];
                    LDSM4(b, S + S_B + g * 16 * 80 + bBase + h * 32);
                    MMA(acc[g][0], a, b[0], b[1]);
                    MMA(acc[g][1], a, b[2], b[3]);
                }
            }
        };

        // ---- paired-chunk pipeline: 2 chunks per sync, 6 stages ----
        issue(0); issue(1); issue(2); issue(3);
#pragma unroll 1
        for (int c = 0; c < nc; c += 2) {
            if (c + 2 < nc) CP_WAIT2(); else CP_WAIT0();
            __syncthreads();
            if (c + 4 < nc) { issue(c + 4); issue(c + 5); }
            if (mywork) {
                compute(c % NSTAGE);
                compute((c + 1) % NSTAGE);
            }
        }
    }

    const int fr = lane >> 2, fc = lane & 3;

    // ---- fused pointwise epilogue ----
    const float* Bias = BiasAll + layer * NTOT;
    const int wb = par ^ 1;
    const __half* zr = g_zh[layer][par];
    __half* zw = g_zh[layer][wb];
#pragma unroll
    for (int rr = 0; rr < 2; ++rr) {
        const int M = m0 + w * 16 + rr * 8 + fr;
        const int r = M >> 6, b = M & 63;
        const bool addb = (r <= t) && (t < RR);
#pragma unroll
        for (int nt = 0; nt < 2; ++nt) {
            const int j0 = jb + nt * 8 + fc * 2;
            float v[NG][2];
#pragma unroll
            for (int g = 0; g < NG; ++g) {
                v[g][0] = acc[g][nt][rr * 2];
                v[g][1] = acc[g][nt][rr * 2 + 1];
                if (addb) { v[g][0] += Bias[g * 256 + j0]; v[g][1] += Bias[g * 256 + j0 + 1]; }
            }
            // h_old = hi + lo, via L2 (persistent launch -> no L1 coherence)
            const size_t zi = (size_t)M * 1024;
            float2 rh = ldcg_h2(&zr[zi + j0]);
            float2 rl = ldcg_h2(&zr[zi + 512 + j0]);
            float2 ch = ldcg_h2(&zr[zi + 256 + j0]);
            float2 cl = ldcg_h2(&zr[zi + 768 + j0]);
            float hro[2] = { rh.x + rl.x, rh.y + rl.y };
            float hco[2] = { ch.x + cl.x, ch.y + cl.y };
            float hr[2], hc[2];
#pragma unroll
            for (int jj = 0; jj < 2; ++jj) {
                float ur = sigmoidf_(v[0][jj]);
                float orr = sigmoidf_(v[1][jj]);
                float uc = sigmoidf_(v[2][jj]);
                float oc = sigmoidf_(v[3][jj]);
                float ir = tanhf(v[4][jj]);
                float ic = tanhf(v[5][jj]);
                hr[jj] = tanhf((1.0f - ur) * hro[jj] + ur * ir) * orr;
                hc[jj] = tanhf((1.0f - uc) * hco[jj] + uc * ic) * oc;
            }
            const int Mr = (((r + 1) & 31) << 6) | b;   // roll(h_col,+1,axis=0)
            uint32_t hrhi = hpack(hr[0], hr[1]);
            float r0f = hr[0] - __half2float(__float2half_rn(hr[0]));
            float r1f = hr[1] - __half2float(__float2half_rn(hr[1]));
            uint32_t hrlo = hpack(r0f, r1f);
            uint32_t hchi = hpack(hc[0], hc[1]);
            float c0f = hc[0] - __half2float(__float2half_rn(hc[0]));
            float c1f = hc[1] - __half2float(__float2half_rn(hc[1]));
            uint32_t hclo = hpack(c0f, c1f);

            *(uint32_t*)&zw[(size_t)M * 1024 + j0] = hrhi;
            *(uint32_t*)&zw[(size_t)M * 1024 + 512 + j0] = hrlo;
            *(uint32_t*)&zw[(size_t)Mr * 1024 + 256 + j0] = hchi;
            *(uint32_t*)&zw[(size_t)Mr * 1024 + 768 + j0] = hclo;

            if (layer == 0) {
                const size_t xb = ((size_t)t * MTOT + M) * 512;
                *(uint32_t*)&g_x1[xb + j0] = hrhi;
                *(uint32_t*)&g_x1[xb + 256 + j0] = hchi;
            } else {
                const size_t ob = ((size_t)M * LLEN + t) * 512;
                *(float2*)&dout[ob + j0] = make_float2(hr[0], hr[1]);
                *(float2*)&dout[ob + 256 + j0] = make_float2(hc[0], hc[1]);
            }
            if (t >= RR - 1) {
                const int k = t - (RR - 1);
                if (r == k)
                    *(float2*)&dout[OFF1 + (((size_t)b * 2 + layer) * RR + k) * HH + j0] =
                        make_float2(hr[0], hr[1]);
                if (r == RR - 1)
                    *(float2*)&dout[OFF2 + (((size_t)b * 2 + layer) * RR + k) * HH + j0] =
                        make_float2(hc[0], hc[1]);
            }
        }
    }
}

// ---------------- persistent wavefront kernel ----------------
// round s: role0 = layer0 t=s (active m-blocks 0..min(s/2+1,16)-1),
//          role1 = layer1 t=s-1. Tiles distributed evenly over 256 CTAs.
__global__ __launch_bounds__(256, 2) void witran_persist(
    const float* __restrict__ BiasAll, float* __restrict__ dout)
{
    extern __shared__ char sm[];
    const int cta = blockIdx.x;
#pragma unroll 1
    for (int s = 0; s < 64; ++s) {
        const int n0 = (s <= 62) ? min(s / 2 + 1, 16) : 0;
        const int n1 = (s >= 1) ? min((s - 1) / 2 + 1, 16) : 0;
        const int total = (n0 + n1) * 16;
#pragma unroll 1
        for (int idx = cta; idx < total; idx += NCTA) {
            int role, mb, jbi, t;
            if (idx < n0 * 16) { role = 0; mb = idx >> 4; jbi = idx & 15; t = s; }
            else { int k2 = idx - n0 * 16; role = 1; mb = k2 >> 4; jbi = k2 & 15; t = s - 1; }
            do_tile(role, t, mb * BM, jbi * BJ, sm, BiasAll, dout);
        }
        grid_barrier();
    }
}

// ---------------- host ----------------
extern "C" void kernel_launch(void* const* d_in, const int* in_sizes, int n_in,
                              void* d_out, int out_size) {
    (void)in_sizes; (void)n_in; (void)out_size;
    const float* inp  = (const float*)d_in[0];
    const float* Wf   = (const float*)d_in[1];
    const float* Wo   = (const float*)d_in[2];
    const float* Bias = (const float*)d_in[3];
    float* out = (float*)d_out;

    cudaFuncSetAttribute(witran_persist, cudaFuncAttributeMaxDynamicSharedMemorySize, SMEMT);

    prep_w<<<512, 256>>>(Wf, Wo);
    prep_x0<<<1024, 256>>>(inp);
    init_all<<<(MTOT * 1024 + 255) / 256, 256>>>();
    zero_tri<<<MTOT, 256>>>(out);

    witran_persist<<<NCTA, 256, SMEMT>>>(Bias, out);
}

// round 14
// speedup vs baseline: 1.0259x; 1.0259x over previous
#include <cuda_runtime.h>
#include <cuda_fp16.h>
#include <math.h>
#include <stdint.h>

// ---------------- problem constants ----------------
#define RR    32
#define LLEN  63
#define HH    256
#define MTOT  2048
#define NG    6
#define NTOT  1536
#define KW0   576            // layer0 K: 512 h + 64 x-pad (8 real)
#define KW1   1024           // layer1 K: 512 h + 512 x1
#define NC0   18             // k32 chunks
#define NC1   32
#define OFF1  66060288ull
#define OFF2  67108864ull
#define NCTA  256

// ---------------- device scratch ----------------
// z-state rows: 1024 fp16 = [hi 512 | lo 512]; hi = [h_row 256 | h_col 256]
__device__ __half g_zh[2][2][MTOT * 1024];                 // [layer][buf]
__device__ __half g_x1[(size_t)LLEN * MTOT * 512];         // layer1 x rows (hi only)
__device__ __half g_x0[LLEN * MTOT * 64];                  // layer0 x rows (hi only)
__device__ __half g_w0[NTOT * KW0];
__device__ __half g_w1[NTOT * KW1];
__device__ int g_bar_count = 0;
__device__ int g_bar_gen = 0;

// ---------------- helpers ----------------
__device__ __forceinline__ uint32_t smem_u32(const void* p) {
    uint32_t a;
    asm("{ .reg .u64 t; cvta.to.shared.u64 t, %1; cvt.u32.u64 %0, t; }" : "=r"(a) : "l"(p));
    return a;
}
__device__ __forceinline__ void cp16(uint32_t s, const void* g) {
    asm volatile("cp.async.cg.shared.global [%0], [%1], 16;" :: "r"(s), "l"(g));
}
#define CP_COMMIT() asm volatile("cp.async.commit_group;")
#define CP_WAIT1()  asm volatile("cp.async.wait_group 1;")
#define CP_WAIT0()  asm volatile("cp.async.wait_group 0;")

#define MMA(accp, a, b0, b1) \
    asm volatile("mma.sync.aligned.m16n8k16.row.col.f32.f16.f16.f32 " \
        "{%0,%1,%2,%3}, {%4,%5,%6,%7}, {%8,%9}, {%0,%1,%2,%3};" \
        : "+f"((accp)[0]), "+f"((accp)[1]), "+f"((accp)[2]), "+f"((accp)[3]) \
        : "r"((a)[0]), "r"((a)[1]), "r"((a)[2]), "r"((a)[3]), "r"(b0), "r"(b1))

#define LDSM4(r, addr) \
    asm volatile("ldmatrix.sync.aligned.m8n8.x4.shared.b16 {%0,%1,%2,%3}, [%4];" \
        : "=r"((r)[0]), "=r"((r)[1]), "=r"((r)[2]), "=r"((r)[3]) : "r"(addr))

__device__ __forceinline__ float sigmoidf_(float x) { return 1.0f / (1.0f + __expf(-x)); }
__device__ __forceinline__ uint32_t hpack(float x, float y) {
    __half2 p = __floats2half2_rn(x, y);
    return *reinterpret_cast<uint32_t*>(&p);
}
// L2-coherent load of a half2 (L1 not coherent across SMs inside one launch)
__device__ __forceinline__ float2 ldcg_h2(const __half* p) {
    uint32_t u;
    asm volatile("ld.global.cg.u32 %0, [%1];" : "=r"(u) : "l"(p));
    __half2 h = *reinterpret_cast<__half2*>(&u);
    return __half22float2(h);
}

// ---------------- smem layout (per stage): k32 chunks, rows padded to 80B ----------------
#define BM 128
#define BJ 16
#define S_A  0                 // A: 128 rows x 80B = 10240
#define S_B  10240             // B: 96 rows x 80B = 7680
#define STAGE 17920
#define NSTAGE 3
#define SMEMT (NSTAGE * STAGE) // 53760 -> 2 CTAs/SM guaranteed

// ---------------- prep kernels ----------------
__global__ void prep_w(const float* __restrict__ Wf, const float* __restrict__ Wo) {
    const int N0 = NTOT * KW0, N1 = NTOT * KW1;
    for (int i = blockIdx.x * blockDim.x + threadIdx.x; i < N0 + N1; i += gridDim.x * blockDim.x) {
        if (i < N0) {
            int n = i / KW0, k = i % KW0;
            float v = (k < 520) ? Wf[(size_t)n * 520 + k] : 0.0f;
            g_w0[i] = __float2half_rn(v);
        } else {
            g_w1[i - N0] = __float2half_rn(Wo[i - N0]);
        }
    }
}

__global__ void prep_x0(const float* __restrict__ inp) {
    const int TOT = LLEN * MTOT * 64;
    for (int i = blockIdx.x * blockDim.x + threadIdx.x; i < TOT; i += gridDim.x * blockDim.x) {
        int k = i & 63;
        int M = (i >> 6) & (MTOT - 1);
        int t = i >> 17;
        int r = M >> 6, b = M & 63, c = t - r;
        float v = 0.0f;
        if (k < 8 && c >= 0 && c < 32)
            v = inp[(((size_t)b * RR + r) * 32 + c) * 8 + k];
        g_x0[i] = __float2half_rn(v);
    }
}

// zero BOTH z double-buffers; inactive rows rely on persistent zeros
__global__ void init_all() {
    int i = blockIdx.x * blockDim.x + threadIdx.x;
    __half z = __float2half_rn(0.0f);
    if (i < MTOT * 1024) {
        g_zh[0][0][i] = z; g_zh[0][1][i] = z;
        g_zh[1][0][i] = z; g_zh[1][1][i] = z;
    }
}
// t<r triangle of output_all is never written by active tiles -> zero it once
__global__ void zero_tri(float* __restrict__ dout) {
    const int M = blockIdx.x;
    const int r = M >> 6;
    float* base = dout + (size_t)M * LLEN * 512;
    const int n = r * 512;
    for (int i = threadIdx.x; i < n; i += blockDim.x) base[i] = 0.0f;
}

// ---------------- grid-wide barrier (all 256 CTAs resident by construction) ----------------
__device__ __forceinline__ void grid_barrier() {
    __threadfence();
    __syncthreads();
    if (threadIdx.x == 0) {
        int my = atomicAdd(&g_bar_gen, 0);
        int tk = atomicAdd(&g_bar_count, 1);
        if (tk == NCTA - 1) {
            atomicExch(&g_bar_count, 0);
            __threadfence();
            atomicAdd(&g_bar_gen, 1);
        } else {
            while (atomicAdd(&g_bar_gen, 0) == my) __nanosleep(64);
        }
        __threadfence();
    }
    __syncthreads();
}

// ---------------- one fused GEMM+pointwise tile ----------------
__device__ __forceinline__ void do_tile(
    int layer, int t, int m0, int jb, char* sm,
    const float* __restrict__ BiasAll, float* __restrict__ dout)
{
    const uint32_t sbase = smem_u32(sm);
    const int tid = threadIdx.x;
    const int lane = tid & 31, w = tid >> 5;
    const int par = t & 1;
    const int nc = layer ? NC1 : NC0;
    const int kw = layer ? KW1 : KW0;
    // half-tile skip: when t == m0/64, rows r = m0/64 + 1 (upper 64, warps 4-7)
    // are identically zero -> those warps skip LDSM/MMA (epilogue still writes zeros)
    const bool mywork = (w < 4) || (t > (m0 >> 6));

    float acc[NG][2][4];
#pragma unroll
    for (int g = 0; g < NG; ++g)
#pragma unroll
        for (int nt = 0; nt < 2; ++nt)
#pragma unroll
            for (int q = 0; q < 4; ++q) acc[g][nt][q] = 0.0f;

    {
        const __half* W = layer ? g_w1 : g_w0;

        // ---- cp.async coords ----
        const int lr = tid >> 2;        // 0..63
        const int lc = tid & 3;         // 16B piece of the 64B chunk-row
        const char* pZ = (const char*)g_zh[layer][par] + (size_t)(m0 + lr) * 2048 + lc * 16;
        const int xstride = layer ? 1024 : 128;
        const char* pX = (layer ? (const char*)g_x1 + ((size_t)t * MTOT) * 1024
                                : (const char*)g_x0 + ((size_t)t * MTOT) * 128)
                         + (size_t)(m0 + lr) * xstride + lc * 16;
        const uint32_t sAoff = S_A + lr * 80 + lc * 16;

        int wr0 = (lr >> 4) * 256 + jb + (lr & 15);
        int v1 = 64 + lr;
        int wr1 = (v1 >> 4) * 256 + jb + (v1 & 15);
        const char* gB0 = (const char*)(W + (size_t)wr0 * kw) + lc * 16;
        const char* gB1 = (const char*)(W + (size_t)wr1 * kw) + lc * 16;
        const uint32_t sB0 = S_B + lr * 80 + lc * 16;
        const uint32_t sB1 = S_B + v1 * 80 + lc * 16;
        const bool doB1 = (lr < 32);

        auto issue = [&](int c, int buf) {
            const uint32_t sb = sbase + buf * STAGE;
            const char* a = (c < 16) ? pZ + (size_t)c * 64
                                     : pX + (size_t)(c - 16) * 64;
            cp16(sb + sAoff, a);
            cp16(sb + sAoff + 64 * 80, a + ((c < 16) ? 64 * 2048 : 64 * xstride));
            const size_t go = (size_t)c * 64;
            cp16(sb + sB0, gB0 + go);
            if (doB1) cp16(sb + sB1, gB1 + go);
            CP_COMMIT();
        };

        // ---- ldmatrix lane coords (warp = m16 x n16) ----
        const int aRow = (lane & 7) + ((lane >> 3) & 1) * 8;
        const int aKoff = ((lane >> 4) & 1) * 16;
        const int bRow = (lane & 7) + (((lane >> 4) & 1) ? 8 : 0);
        const int bKoff = ((lane >> 3) & 1) * 16;
        const uint32_t aBase = (w * 16 + aRow) * 80 + aKoff;
        const uint32_t bBase = bRow * 80 + bKoff;

        auto compute = [&](int buf) {
            const uint32_t S = sbase + buf * STAGE;
#pragma unroll
            for (int h = 0; h < 2; ++h) {
                uint32_t a[4];
                LDSM4(a, S + S_A + aBase + h * 32);
#pragma unroll
                for (int g = 0; g < NG; ++g) {
                    uint32_t b[4];
                    LDSM4(b, S + S_B + g * 16 * 80 + bBase + h * 32);
                    MMA(acc[g][0], a, b[0], b[1]);
                    MMA(acc[g][1], a, b[2], b[3]);
                }
            }
        };

        // ---- 3-stage pipelined K loop (R11-proven cadence) ----
        issue(0, 0);
        issue(1, 1);
#pragma unroll 1
        for (int c = 0; c < nc; ++c) {
            if (c < nc - 1) CP_WAIT1(); else CP_WAIT0();
            __syncthreads();
            if (c + 2 < nc) issue(c + 2, (c + 2) % NSTAGE);
            if (mywork) compute(c % NSTAGE);
        }
    }

    const int fr = lane >> 2, fc = lane & 3;

    // ---- fused pointwise epilogue ----
    const float* Bias = BiasAll + layer * NTOT;
    const int wb = par ^ 1;
    const __half* zr = g_zh[layer][par];
    __half* zw = g_zh[layer][wb];
#pragma unroll
    for (int rr = 0; rr < 2; ++rr) {
        const int M = m0 + w * 16 + rr * 8 + fr;
        const int r = M >> 6, b = M & 63;
        const bool addb = (r <= t) && (t < RR);
#pragma unroll
        for (int nt = 0; nt < 2; ++nt) {
            const int j0 = jb + nt * 8 + fc * 2;
            float v[NG][2];
#pragma unroll
            for (int g = 0; g < NG; ++g) {
                v[g][0] = acc[g][nt][rr * 2];
                v[g][1] = acc[g][nt][rr * 2 + 1];
                if (addb) { v[g][0] += Bias[g * 256 + j0]; v[g][1] += Bias[g * 256 + j0 + 1]; }
            }
            // h_old = hi + lo, via L2 (persistent launch -> no L1 coherence)
            const size_t zi = (size_t)M * 1024;
            float2 rh = ldcg_h2(&zr[zi + j0]);
            float2 rl = ldcg_h2(&zr[zi + 512 + j0]);
            float2 ch = ldcg_h2(&zr[zi + 256 + j0]);
            float2 cl = ldcg_h2(&zr[zi + 768 + j0]);
            float hro[2] = { rh.x + rl.x, rh.y + rl.y };
            float hco[2] = { ch.x + cl.x, ch.y + cl.y };
            float hr[2], hc[2];
#pragma unroll
            for (int jj = 0; jj < 2; ++jj) {
                float ur = sigmoidf_(v[0][jj]);
                float orr = sigmoidf_(v[1][jj]);
                float uc = sigmoidf_(v[2][jj]);
                float oc = sigmoidf_(v[3][jj]);
                float ir = tanhf(v[4][jj]);
                float ic = tanhf(v[5][jj]);
                hr[jj] = tanhf((1.0f - ur) * hro[jj] + ur * ir) * orr;
                hc[jj] = tanhf((1.0f - uc) * hco[jj] + uc * ic) * oc;
            }
            const int Mr = (((r + 1) & 31) << 6) | b;   // roll(h_col,+1,axis=0)
            uint32_t hrhi = hpack(hr[0], hr[1]);
            float r0f = hr[0] - __half2float(__float2half_rn(hr[0]));
            float r1f = hr[1] - __half2float(__float2half_rn(hr[1]));
            uint32_t hrlo = hpack(r0f, r1f);
            uint32_t hchi = hpack(hc[0], hc[1]);
            float c0f = hc[0] - __half2float(__float2half_rn(hc[0]));
            float c1f = hc[1] - __half2float(__float2half_rn(hc[1]));
            uint32_t hclo = hpack(c0f, c1f);

            *(uint32_t*)&zw[(size_t)M * 1024 + j0] = hrhi;
            *(uint32_t*)&zw[(size_t)M * 1024 + 512 + j0] = hrlo;
            *(uint32_t*)&zw[(size_t)Mr * 1024 + 256 + j0] = hchi;
            *(uint32_t*)&zw[(size_t)Mr * 1024 + 768 + j0] = hclo;

            if (layer == 0) {
                const size_t xb = ((size_t)t * MTOT + M) * 512;
                *(uint32_t*)&g_x1[xb + j0] = hrhi;
                *(uint32_t*)&g_x1[xb + 256 + j0] = hchi;
            } else {
                const size_t ob = ((size_t)M * LLEN + t) * 512;
                *(float2*)&dout[ob + j0] = make_float2(hr[0], hr[1]);
                *(float2*)&dout[ob + 256 + j0] = make_float2(hc[0], hc[1]);
            }
            if (t >= RR - 1) {
                const int k = t - (RR - 1);
                if (r == k)
                    *(float2*)&dout[OFF1 + (((size_t)b * 2 + layer) * RR + k) * HH + j0] =
                        make_float2(hr[0], hr[1]);
                if (r == RR - 1)
                    *(float2*)&dout[OFF2 + (((size_t)b * 2 + layer) * RR + k) * HH + j0] =
                        make_float2(hc[0], hc[1]);
            }
        }
    }
}

// ---------------- persistent wavefront kernel ----------------
// round s: role0 = layer0 t=s (active m-blocks 0..min(s/2+1,16)-1),
//          role1 = layer1 t=s-1. Tiles distributed evenly over 256 CTAs.
__global__ __launch_bounds__(256, 2) void witran_persist(
    const float* __restrict__ BiasAll, float* __restrict__ dout)
{
    extern __shared__ char sm[];
    const int cta = blockIdx.x;
#pragma unroll 1
    for (int s = 0; s < 64; ++s) {
        const int n0 = (s <= 62) ? min(s / 2 + 1, 16) : 0;
        const int n1 = (s >= 1) ? min((s - 1) / 2 + 1, 16) : 0;
        const int total = (n0 + n1) * 16;
#pragma unroll 1
        for (int idx = cta; idx < total; idx += NCTA) {
            int role, mb, jbi, t;
            if (idx < n0 * 16) { role = 0; mb = idx >> 4; jbi = idx & 15; t = s; }
            else { int k2 = idx - n0 * 16; role = 1; mb = k2 >> 4; jbi = k2 & 15; t = s - 1; }
            do_tile(role, t, mb * BM, jbi * BJ, sm, BiasAll, dout);
        }
        grid_barrier();
    }
}

// ---------------- host ----------------
extern "C" void kernel_launch(void* const* d_in, const int* in_sizes, int n_in,
                              void* d_out, int out_size) {
    (void)in_sizes; (void)n_in; (void)out_size;
    const float* inp  = (const float*)d_in[0];
    const float* Wf   = (const float*)d_in[1];
    const float* Wo   = (const float*)d_in[2];
    const float* Bias = (const float*)d_in[3];
    float* out = (float*)d_out;

    cudaFuncSetAttribute(witran_persist, cudaFuncAttributeMaxDynamicSharedMemorySize, SMEMT);

    prep_w<<<512, 256>>>(Wf, Wo);
    prep_x0<<<1024, 256>>>(inp);
    init_all<<<(MTOT * 1024 + 255) / 256, 256>>>();
    zero_tri<<<MTOT, 256>>>(out);

    witran_persist<<<NCTA, 256, SMEMT>>>(Bias, out);
}

// round 17
// speedup vs baseline: 1.1725x; 1.1429x over previous
#include <cuda_runtime.h>
#include <cuda_fp16.h>
#include <math.h>
#include <stdint.h>

// ---------------- problem constants ----------------
#define RR    32
#define LLEN  63
#define HH    256
#define MTOT  2048
#define NG    6
#define NTOT  1536
#define KW0   576            // layer0 K: 512 h + 64 x-pad (8 real)
#define KW1   1024           // layer1 K: 512 h + 512 x1
#define NC0   18             // k32 chunks
#define NC1   32
#define OFF1  66060288ull
#define OFF2  67108864ull
#define NCTA  256

// ---------------- device scratch ----------------
// z-state rows: 1024 fp16 = [hi 512 | lo 512]; hi = [h_row 256 | h_col 256]
__device__ __half g_zh[2][2][MTOT * 1024];                 // [layer][buf]
__device__ __half g_x1[(size_t)LLEN * MTOT * 512];         // layer1 x rows (hi only)
__device__ __half g_x0[LLEN * MTOT * 64];                  // layer0 x rows (hi only)
__device__ __half g_w0[NTOT * KW0];
__device__ __half g_w1[NTOT * KW1];
__device__ int g_bar_count = 0;
__device__ int g_bar_gen = 0;

// ---------------- helpers ----------------
__device__ __forceinline__ uint32_t smem_u32(const void* p) {
    uint32_t a;
    asm("{ .reg .u64 t; cvta.to.shared.u64 t, %1; cvt.u32.u64 %0, t; }" : "=r"(a) : "l"(p));
    return a;
}
__device__ __forceinline__ void cp16(uint32_t s, const void* g) {
    asm volatile("cp.async.cg.shared.global [%0], [%1], 16;" :: "r"(s), "l"(g));
}
__device__ __forceinline__ void mbar_init(uint32_t a, uint32_t cnt) {
    asm volatile("mbarrier.init.shared.b64 [%0], %1;" :: "r"(a), "r"(cnt) : "memory");
}
__device__ __forceinline__ void mbar_arrive(uint32_t a) {
    asm volatile("{\n\t.reg .b64 t;\n\tmbarrier.arrive.shared.b64 t, [%0];\n\t}"
                 :: "r"(a) : "memory");
}
// .noinc: the async arrive COUNTS toward the expected 256 arrivals
__device__ __forceinline__ void cpasync_arrive(uint32_t a) {
    asm volatile("cp.async.mbarrier.arrive.noinc.shared.b64 [%0];" :: "r"(a) : "memory");
}
__device__ __forceinline__ void mbar_wait(uint32_t a, uint32_t phase) {
    asm volatile(
        "{\n\t.reg .pred P;\n\t"
        "LW_%=:\n\t"
        "mbarrier.try_wait.parity.shared::cta.b64 P, [%0], %1;\n\t"
        "@!P bra LW_%=;\n\t}"
        :: "r"(a), "r"(phase) : "memory");
}

#define MMA(accp, a, b0, b1) \
    asm volatile("mma.sync.aligned.m16n8k16.row.col.f32.f16.f16.f32 " \
        "{%0,%1,%2,%3}, {%4,%5,%6,%7}, {%8,%9}, {%0,%1,%2,%3};" \
        : "+f"((accp)[0]), "+f"((accp)[1]), "+f"((accp)[2]), "+f"((accp)[3]) \
        : "r"((a)[0]), "r"((a)[1]), "r"((a)[2]), "r"((a)[3]), "r"(b0), "r"(b1))

#define LDSM4(r, addr) \
    asm volatile("ldmatrix.sync.aligned.m8n8.x4.shared.b16 {%0,%1,%2,%3}, [%4];" \
        : "=r"((r)[0]), "=r"((r)[1]), "=r"((r)[2]), "=r"((r)[3]) : "r"(addr))

__device__ __forceinline__ float sigmoidf_(float x) { return 1.0f / (1.0f + __expf(-x)); }
__device__ __forceinline__ uint32_t hpack(float x, float y) {
    __half2 p = __floats2half2_rn(x, y);
    return *reinterpret_cast<uint32_t*>(&p);
}
// L2-coherent load of a half2 (L1 not coherent across SMs inside one launch)
__device__ __forceinline__ float2 ldcg_h2(const __half* p) {
    uint32_t u;
    asm volatile("ld.global.cg.u32 %0, [%1];" : "=r"(u) : "l"(p));
    __half2 h = *reinterpret_cast<__half2*>(&u);
    return __half22float2(h);
}

// ---------------- smem layout: 6 stages of k32 chunks, rows padded to 80B ----------------
#define BM 128
#define BJ 16
#define S_A  0                 // A: 128 rows x 80B = 10240
#define S_B  10240             // B: 96 rows x 80B = 7680
#define STAGE 17920
#define NSTAGE 6
#define MB_OFF 0               // mbarriers: full[6] at 0..47, empty[6] at 48..95
#define ST_OFF 128
#define SMEMT (ST_OFF + NSTAGE * STAGE)   // 107648 -> 2 CTAs/SM (215KB)

// ---------------- prep kernels ----------------
__global__ void prep_w(const float* __restrict__ Wf, const float* __restrict__ Wo) {
    const int N0 = NTOT * KW0, N1 = NTOT * KW1;
    for (int i = blockIdx.x * blockDim.x + threadIdx.x; i < N0 + N1; i += gridDim.x * blockDim.x) {
        if (i < N0) {
            int n = i / KW0, k = i % KW0;
            float v = (k < 520) ? Wf[(size_t)n * 520 + k] : 0.0f;
            g_w0[i] = __float2half_rn(v);
        } else {
            g_w1[i - N0] = __float2half_rn(Wo[i - N0]);
        }
    }
}

__global__ void prep_x0(const float* __restrict__ inp) {
    const int TOT = LLEN * MTOT * 64;
    for (int i = blockIdx.x * blockDim.x + threadIdx.x; i < TOT; i += gridDim.x * blockDim.x) {
        int k = i & 63;
        int M = (i >> 6) & (MTOT - 1);
        int t = i >> 17;
        int r = M >> 6, b = M & 63, c = t - r;
        float v = 0.0f;
        if (k < 8 && c >= 0 && c < 32)
            v = inp[(((size_t)b * RR + r) * 32 + c) * 8 + k];
        g_x0[i] = __float2half_rn(v);
    }
}

// zero BOTH z double-buffers; inactive rows rely on persistent zeros
__global__ void init_all() {
    int i = blockIdx.x * blockDim.x + threadIdx.x;
    __half z = __float2half_rn(0.0f);
    if (i < MTOT * 1024) {
        g_zh[0][0][i] = z; g_zh[0][1][i] = z;
        g_zh[1][0][i] = z; g_zh[1][1][i] = z;
    }
}
// t<r triangle of output_all is never written by active tiles -> zero it once
__global__ void zero_tri(float* __restrict__ dout) {
    const int M = blockIdx.x;
    const int r = M >> 6;
    float* base = dout + (size_t)M * LLEN * 512;
    const int n = r * 512;
    for (int i = threadIdx.x; i < n; i += blockDim.x) base[i] = 0.0f;
}

// ---------------- grid-wide barrier (all 256 CTAs resident by construction) ----------------
__device__ __forceinline__ void grid_barrier() {
    __threadfence();
    __syncthreads();
    if (threadIdx.x == 0) {
        int my = atomicAdd(&g_bar_gen, 0);
        int tk = atomicAdd(&g_bar_count, 1);
        if (tk == NCTA - 1) {
            atomicExch(&g_bar_count, 0);
            __threadfence();
            atomicAdd(&g_bar_gen, 1);
        } else {
            while (atomicAdd(&g_bar_gen, 0) == my) __nanosleep(64);
        }
        __threadfence();
    }
    __syncthreads();
}

// ---------------- one fused GEMM+pointwise tile (mbarrier pipeline) ----------------
__device__ __forceinline__ void do_tile(
    int layer, int t, int m0, int jb, char* sm,
    const float* __restrict__ BiasAll, float* __restrict__ dout)
{
    const uint32_t sbase = smem_u32(sm);
    const int tid = threadIdx.x;
    const int lane = tid & 31, w = tid >> 5;
    const int par = t & 1;
    const int nc = layer ? NC1 : NC0;
    const int kw = layer ? KW1 : KW0;
    // half-tile skip: when t == m0/64, upper 64 rows (warps 4-7) are zero
    const bool mywork = (w < 4) || (t > (m0 >> 6));

    // tile boundary: all warps done with previous tile's smem, then re-init barriers
    __syncthreads();
    if (tid == 0) {
#pragma unroll
        for (int s2 = 0; s2 < NSTAGE; ++s2) {
            mbar_init(sbase + MB_OFF + s2 * 8, 256);
            mbar_init(sbase + MB_OFF + 48 + s2 * 8, 256);
        }
    }
    __syncthreads();

    float acc[NG][2][4];
#pragma unroll
    for (int g = 0; g < NG; ++g)
#pragma unroll
        for (int nt = 0; nt < 2; ++nt)
#pragma unroll
            for (int q = 0; q < 4; ++q) acc[g][nt][q] = 0.0f;

    {
        const __half* W = layer ? g_w1 : g_w0;

        // ---- cp.async coords ----
        const int lr = tid >> 2;        // 0..63
        const int lc = tid & 3;         // 16B piece of the 64B chunk-row
        const char* pZ = (const char*)g_zh[layer][par] + (size_t)(m0 + lr) * 2048 + lc * 16;
        const int xstride = layer ? 1024 : 128;
        const char* pX = (layer ? (const char*)g_x1 + ((size_t)t * MTOT) * 1024
                                : (const char*)g_x0 + ((size_t)t * MTOT) * 128)
                         + (size_t)(m0 + lr) * xstride + lc * 16;
        const uint32_t sAoff = ST_OFF + S_A + lr * 80 + lc * 16;

        int wr0 = (lr >> 4) * 256 + jb + (lr & 15);
        int v1 = 64 + lr;
        int wr1 = (v1 >> 4) * 256 + jb + (v1 & 15);
        const char* gB0 = (const char*)(W + (size_t)wr0 * kw) + lc * 16;
        const char* gB1 = (const char*)(W + (size_t)wr1 * kw) + lc * 16;
        const uint32_t sB0 = ST_OFF + S_B + lr * 80 + lc * 16;
        const uint32_t sB1 = ST_OFF + S_B + v1 * 80 + lc * 16;
        const bool doB1 = (lr < 32);

        auto fill = [&](int f) {
            const int slot = f % NSTAGE;
            const uint32_t sb = sbase + slot * STAGE;
            const char* a = (f < 16) ? pZ + (size_t)f * 64
                                     : pX + (size_t)(f - 16) * 64;
            cp16(sb + sAoff, a);
            cp16(sb + sAoff + 64 * 80, a + ((f < 16) ? 64 * 2048 : 64 * xstride));
            const size_t go = (size_t)f * 64;
            cp16(sb + sB0, gB0 + go);
            if (doB1) cp16(sb + sB1, gB1 + go);
            cpasync_arrive(sbase + MB_OFF + slot * 8);   // full[slot], .noinc
        };

        // ---- ldmatrix lane coords (warp = m16 x n16) ----
        const int aRow = (lane & 7) + ((lane >> 3) & 1) * 8;
        const int aKoff = ((lane >> 4) & 1) * 16;
        const int bRow = (lane & 7) + (((lane >> 4) & 1) ? 8 : 0);
        const int bKoff = ((lane >> 3) & 1) * 16;
        const uint32_t aBase = (w * 16 + aRow) * 80 + aKoff;
        const uint32_t bBase = bRow * 80 + bKoff;

        auto compute = [&](int slot) {
            const uint32_t S = sbase + slot * STAGE + ST_OFF;
#pragma unroll
            for (int h = 0; h < 2; ++h) {
                uint32_t a[4];
                LDSM4(a, S + S_A + aBase + h * 32);
#pragma unroll
                for (int g = 0; g < NG; ++g) {
                    uint32_t b[4];
                    LDSM4(b, S + S_B + g * 16 * 80 + bBase + h * 32);
                    MMA(acc[g][0], a, b[0], b[1]);
                    MMA(acc[g][1], a, b[2], b[3]);
                }
            }
        };

        // ---- decoupled pipeline: no __syncthreads inside the loop ----
        fill(0); fill(1); fill(2); fill(3);
#pragma unroll 1
        for (int c = 0; c < nc; ++c) {
            const int slot = c % NSTAGE;
            mbar_wait(sbase + MB_OFF + slot * 8, (c / NSTAGE) & 1);      // full
            if (mywork) compute(slot);
            mbar_arrive(sbase + MB_OFF + 48 + slot * 8);                 // empty
            const int f = c + 4;
            if (f < nc) {
                const int fs = f % NSTAGE;
                if (f >= NSTAGE)
                    mbar_wait(sbase + MB_OFF + 48 + fs * 8, ((f / NSTAGE) - 1) & 1);
                fill(f);
            }
        }
    }

    const int fr = lane >> 2, fc = lane & 3;

    // ---- fused pointwise epilogue (per-warp, overlaps other warps' compute) ----
    const float* Bias = BiasAll + layer * NTOT;
    const int wb = par ^ 1;
    const __half* zr = g_zh[layer][par];
    __half* zw = g_zh[layer][wb];
#pragma unroll
    for (int rr = 0; rr < 2; ++rr) {
        const int M = m0 + w * 16 + rr * 8 + fr;
        const int r = M >> 6, b = M & 63;
        const bool addb = (r <= t) && (t < RR);
#pragma unroll
        for (int nt = 0; nt < 2; ++nt) {
            const int j0 = jb + nt * 8 + fc * 2;
            float v[NG][2];
#pragma unroll
            for (int g = 0; g < NG; ++g) {
                v[g][0] = acc[g][nt][rr * 2];
                v[g][1] = acc[g][nt][rr * 2 + 1];
                if (addb) { v[g][0] += Bias[g * 256 + j0]; v[g][1] += Bias[g * 256 + j0 + 1]; }
            }
            // h_old = hi + lo, via L2 (persistent launch -> no L1 coherence)
            const size_t zi = (size_t)M * 1024;
            float2 rh = ldcg_h2(&zr[zi + j0]);
            float2 rl = ldcg_h2(&zr[zi + 512 + j0]);
            float2 ch = ldcg_h2(&zr[zi + 256 + j0]);
            float2 cl = ldcg_h2(&zr[zi + 768 + j0]);
            float hro[2] = { rh.x + rl.x, rh.y + rl.y };
            float hco[2] = { ch.x + cl.x, ch.y + cl.y };
            float hr[2], hc[2];
#pragma unroll
            for (int jj = 0; jj < 2; ++jj) {
                float ur = sigmoidf_(v[0][jj]);
                float orr = sigmoidf_(v[1][jj]);
                float uc = sigmoidf_(v[2][jj]);
                float oc = sigmoidf_(v[3][jj]);
                float ir = tanhf(v[4][jj]);
                float ic = tanhf(v[5][jj]);
                hr[jj] = tanhf((1.0f - ur) * hro[jj] + ur * ir) * orr;
                hc[jj] = tanhf((1.0f - uc) * hco[jj] + uc * ic) * oc;
            }
            const int Mr = (((r + 1) & 31) << 6) | b;   // roll(h_col,+1,axis=0)
            uint32_t hrhi = hpack(hr[0], hr[1]);
            float r0f = hr[0] - __half2float(__float2half_rn(hr[0]));
            float r1f = hr[1] - __half2float(__float2half_rn(hr[1]));
            uint32_t hrlo = hpack(r0f, r1f);
            uint32_t hchi = hpack(hc[0], hc[1]);
            float c0f = hc[0] - __half2float(__float2half_rn(hc[0]));
            float c1f = hc[1] - __half2float(__float2half_rn(hc[1]));
            uint32_t hclo = hpack(c0f, c1f);

            *(uint32_t*)&zw[(size_t)M * 1024 + j0] = hrhi;
            *(uint32_t*)&zw[(size_t)M * 1024 + 512 + j0] = hrlo;
            *(uint32_t*)&zw[(size_t)Mr * 1024 + 256 + j0] = hchi;
            *(uint32_t*)&zw[(size_t)Mr * 1024 + 768 + j0] = hclo;

            if (layer == 0) {
                const size_t xb = ((size_t)t * MTOT + M) * 512;
                *(uint32_t*)&g_x1[xb + j0] = hrhi;
                *(uint32_t*)&g_x1[xb + 256 + j0] = hchi;
            } else {
                const size_t ob = ((size_t)M * LLEN + t) * 512;
                *(float2*)&dout[ob + j0] = make_float2(hr[0], hr[1]);
                *(float2*)&dout[ob + 256 + j0] = make_float2(hc[0], hc[1]);
            }
            if (t >= RR - 1) {
                const int k = t - (RR - 1);
                if (r == k)
                    *(float2*)&dout[OFF1 + (((size_t)b * 2 + layer) * RR + k) * HH + j0] =
                        make_float2(hr[0], hr[1]);
                if (r == RR - 1)
                    *(float2*)&dout[OFF2 + (((size_t)b * 2 + layer) * RR + k) * HH + j0] =
                        make_float2(hc[0], hc[1]);
            }
        }
    }
}

// ---------------- persistent wavefront kernel ----------------
// round s: role0 = layer0 t=s (active m-blocks 0..min(s/2+1,16)-1),
//          role1 = layer1 t=s-1. Tiles distributed evenly over 256 CTAs.
__global__ __launch_bounds__(256, 2) void witran_persist(
    const float* __restrict__ BiasAll, float* __restrict__ dout)
{
    extern __shared__ char sm[];
    const int cta = blockIdx.x;
#pragma unroll 1
    for (int s = 0; s < 64; ++s) {
        const int n0 = (s <= 62) ? min(s / 2 + 1, 16) : 0;
        const int n1 = (s >= 1) ? min((s - 1) / 2 + 1, 16) : 0;
        const int total = (n0 + n1) * 16;
#pragma unroll 1
        for (int idx = cta; idx < total; idx += NCTA) {
            int role, mb, jbi, t;
            if (idx < n0 * 16) { role = 0; mb = idx >> 4; jbi = idx & 15; t = s; }
            else { int k2 = idx - n0 * 16; role = 1; mb = k2 >> 4; jbi = k2 & 15; t = s - 1; }
            do_tile(role, t, mb * BM, jbi * BJ, sm, BiasAll, dout);
        }
        grid_barrier();
    }
}

// ---------------- host ----------------
extern "C" void kernel_launch(void* const* d_in, const int* in_sizes, int n_in,
                              void* d_out, int out_size) {
    (void)in_sizes; (void)n_in; (void)out_size;
    const float* inp  = (const float*)d_in[0];
    const float* Wf   = (const float*)d_in[1];
    const float* Wo   = (const float*)d_in[2];
    const float* Bias = (const float*)d_in[3];
    float* out = (float*)d_out;

    cudaFuncSetAttribute(witran_persist, cudaFuncAttributeMaxDynamicSharedMemorySize, SMEMT);

    prep_w<<<512, 256>>>(Wf, Wo);
    prep_x0<<<1024, 256>>>(inp);
    init_all<<<(MTOT * 1024 + 255) / 256, 256>>>();
    zero_tri<<<MTOT, 256>>>(out);

    witran_persist<<<NCTA, 256, SMEMT>>>(Bias, out);
}